// round 4
// baseline (speedup 1.0000x reference)
#include <cuda_runtime.h>

// ---------------------------------------------------------------------------
// Problem constants
// ---------------------------------------------------------------------------
constexpr int Bb    = 4;
constexpr int Uu    = 64;
constexpr int Vv    = 256;
constexpr int BU    = Bb * Uu;     // 256
constexpr int BV    = Bb * Vv;     // 1024
constexpr int D     = 768;         // STATE_DIM == IN_DIM
constexpr int CD    = 384;         // CODE_DIM
constexpr int INNER = 512;         // NUM_HEADS * HEAD_DIM
constexpr int Hh    = 8;

// ---------------------------------------------------------------------------
// Scratch (device globals; no allocation allowed)
// ---------------------------------------------------------------------------
__device__ float g_MQ[BU * D];
__device__ float g_MK[BU * D];
__device__ float g_MV[BU * D];
__device__ float g_ME[BU * INNER];
__device__ float g_qmod[BU * D];
__device__ float g_Q[BU * INNER];
__device__ float g_sln[BV * D];
__device__ float g_A[BU * Hh * D];       // [(bu*8+h)][d]
__device__ float g_S[Bb * 512 * 256];    // [b][(u*8+h)][v]
__device__ float g_T[BU * Hh * D];       // [(bu*8+h)][d]
__device__ float g_msg[BU * INNER];

// ---------------------------------------------------------------------------
// Generic tiled fp32 GEMM: C[r,c] = epi( sum_k A[r,k]*B[k,c], z, r, c )
// BT=true means B element (k,n) lives at B[n*ldb + k] (transposed access).
// blockIdx.z = batch; per-batch pointer strides sA/sB/sC.
// All M,N,K in this problem are multiples of 64/64/32 -> no bounds checks.
// ---------------------------------------------------------------------------
constexpr int BM = 64, BN = 64, BK = 32, TM = 4, TN = 4;

template <bool BT, class Epi>
__global__ void __launch_bounds__(256)
gemm_k(const float* __restrict__ Ag, const float* __restrict__ Bg,
       float* __restrict__ Cg, int K, int lda, int ldb, int ldc,
       long sA, long sB, long sC, Epi epi)
{
    const int z = blockIdx.z;
    const float* A = Ag + (long)z * sA;
    const float* Bp = Bg + (long)z * sB;
    float* C = Cg + (long)z * sC;
    const int bm = blockIdx.y * BM;
    const int bn = blockIdx.x * BN;

    __shared__ __align__(16) float As[BK][BM + 4];
    __shared__ __align__(16) float Bs[BK][BN + 4];

    const int tid = threadIdx.x;
    const int tx = tid & 15;
    const int ty = tid >> 4;

    float acc[TM][TN] = {};

    for (int k0 = 0; k0 < K; k0 += BK) {
        // A tile: coalesced along k
        #pragma unroll
        for (int i = 0; i < (BM * BK) / 256; ++i) {
            int idx = tid + i * 256;
            int m = idx >> 5, k = idx & 31;
            As[k][m] = A[(long)(bm + m) * lda + (k0 + k)];
        }
        // B tile
        #pragma unroll
        for (int i = 0; i < (BN * BK) / 256; ++i) {
            int idx = tid + i * 256;
            if constexpr (BT) {
                int n = idx >> 5, k = idx & 31;      // coalesced along k
                Bs[k][n] = Bp[(long)(bn + n) * ldb + (k0 + k)];
            } else {
                int k = idx >> 6, n = idx & 63;      // coalesced along n
                Bs[k][n] = Bp[(long)(k0 + k) * ldb + (bn + n)];
            }
        }
        __syncthreads();

        #pragma unroll
        for (int k = 0; k < BK; ++k) {
            float4 av = *(const float4*)&As[k][ty * TM];
            float4 bv = *(const float4*)&Bs[k][tx * TN];
            float a4[4] = {av.x, av.y, av.z, av.w};
            float b4[4] = {bv.x, bv.y, bv.z, bv.w};
            #pragma unroll
            for (int i = 0; i < TM; ++i)
                #pragma unroll
                for (int j = 0; j < TN; ++j)
                    acc[i][j] = fmaf(a4[i], b4[j], acc[i][j]);
        }
        __syncthreads();
    }

    #pragma unroll
    for (int i = 0; i < TM; ++i) {
        int r = bm + ty * TM + i;
        #pragma unroll
        for (int j = 0; j < TN; ++j) {
            int c = bn + tx * TN + j;
            C[(long)r * ldc + c] = epi(acc[i][j], z, r, c);
        }
    }
}

// ---------------------------------------------------------------------------
// Epilogues
// ---------------------------------------------------------------------------
struct EpiNone {
    __device__ float operator()(float a, int, int, int) const { return a; }
};
struct EpiBias {  // + b[col]
    const float* b;
    __device__ float operator()(float a, int, int, int c) const { return a + b[c]; }
};
struct EpiScale {
    float s;
    __device__ float operator()(float a, int, int, int) const { return a * s; }
};
struct EpiMulRowMod {  // * (1 + m[row*768 + col])   (G3: A = qWk * mk)
    const float* m;
    __device__ float operator()(float a, int, int r, int c) const {
        return a * (1.f + m[r * 768 + c]);
    }
};
struct EpiMulT {  // G5: T *= (1 + MV[bu*768 + d]); rows are (u*8+h) within batch b=z
    const float* mv;
    __device__ float operator()(float a, int z, int r, int c) const {
        int bu = z * 64 + (r >> 3);
        return a * (1.f + mv[bu * 768 + c]);
    }
};
struct EpiMsg {  // G6: (acc + bv[h*64+c]) * (1 + ME[bu*512 + h*64+c]); z = h
    const float* bv;
    const float* me;
    __device__ float operator()(float a, int z, int r, int c) const {
        int idx = z * 64 + c;
        return (a + bv[idx]) * (1.f + me[r * 512 + idx]);
    }
};
struct EpiFinal {  // G7: receiver + gamma * (acc + be)
    const float* rec;
    const float* be;
    const float* gam;
    __device__ float operator()(float a, int, int r, int c) const {
        return rec[(long)r * 768 + c] + gam[c] * (a + be[c]);
    }
};

// ---------------------------------------------------------------------------
// LayerNorm kernels (row = one block of 256 threads, 3 elems/thread, dim 768)
// var = E[x^2] - mu^2 (population, matches jnp.var), eps = 1e-5
// ---------------------------------------------------------------------------
__device__ __forceinline__ void reduce2_768(float& s, float& s2)
{
    __shared__ float2 sm[8];
    #pragma unroll
    for (int o = 16; o; o >>= 1) {
        s  += __shfl_xor_sync(0xffffffffu, s,  o);
        s2 += __shfl_xor_sync(0xffffffffu, s2, o);
    }
    if ((threadIdx.x & 31) == 0) sm[threadIdx.x >> 5] = make_float2(s, s2);
    __syncthreads();
    s = 0.f; s2 = 0.f;
    #pragma unroll
    for (int i = 0; i < 8; ++i) { s += sm[i].x; s2 += sm[i].y; }
}

__global__ void ln_k(const float* __restrict__ xin, const float* __restrict__ g,
                     const float* __restrict__ bb, float* __restrict__ out)
{
    int row = blockIdx.x;
    const float* x = xin + (long)row * 768;
    float v[3], s = 0.f, s2 = 0.f;
    #pragma unroll
    for (int i = 0; i < 3; ++i) {
        v[i] = x[threadIdx.x + 256 * i];
        s += v[i]; s2 += v[i] * v[i];
    }
    reduce2_768(s, s2);
    float mu = s * (1.f / 768.f);
    float var = s2 * (1.f / 768.f) - mu * mu;
    float inv = rsqrtf(var + 1e-5f);
    #pragma unroll
    for (int i = 0; i < 3; ++i) {
        int d = threadIdx.x + 256 * i;
        out[(long)row * 768 + d] = (v[i] - mu) * inv * g[d] + bb[d];
    }
}

__global__ void ln_qmod_k(const float* __restrict__ rec, const float* __restrict__ g,
                          const float* __restrict__ bb, const float* __restrict__ MQ,
                          float* __restrict__ qmod)
{
    int row = blockIdx.x;
    const float* x = rec + (long)row * 768;
    float v[3], s = 0.f, s2 = 0.f;
    #pragma unroll
    for (int i = 0; i < 3; ++i) {
        v[i] = x[threadIdx.x + 256 * i];
        s += v[i]; s2 += v[i] * v[i];
    }
    reduce2_768(s, s2);
    float mu = s * (1.f / 768.f);
    float var = s2 * (1.f / 768.f) - mu * mu;
    float inv = rsqrtf(var + 1e-5f);
    #pragma unroll
    for (int i = 0; i < 3; ++i) {
        int d = threadIdx.x + 256 * i;
        float y = (v[i] - mu) * inv * g[d] + bb[d];
        qmod[(long)row * 768 + d] = y * (1.f + MQ[(long)row * 768 + d]);
    }
}

// ---------------------------------------------------------------------------
// Softmax over v (256) — one block per (b, u, h) row
// ---------------------------------------------------------------------------
__global__ void softmax_k(float* __restrict__ S)
{
    int row = blockIdx.x;  // 0..2047
    float v = S[(long)row * 256 + threadIdx.x];
    __shared__ float sm[8];

    float m = v;
    #pragma unroll
    for (int o = 16; o; o >>= 1) m = fmaxf(m, __shfl_xor_sync(0xffffffffu, m, o));
    if ((threadIdx.x & 31) == 0) sm[threadIdx.x >> 5] = m;
    __syncthreads();
    m = sm[0];
    #pragma unroll
    for (int i = 1; i < 8; ++i) m = fmaxf(m, sm[i]);
    float e = __expf(v - m);
    __syncthreads();

    float su = e;
    #pragma unroll
    for (int o = 16; o; o >>= 1) su += __shfl_xor_sync(0xffffffffu, su, o);
    if ((threadIdx.x & 31) == 0) sm[threadIdx.x >> 5] = su;
    __syncthreads();
    su = 0.f;
    #pragma unroll
    for (int i = 0; i < 8; ++i) su += sm[i];

    S[(long)row * 256 + threadIdx.x] = e / su;
}

// ---------------------------------------------------------------------------
// Launch
// ---------------------------------------------------------------------------
static float* sym(const void* s)
{
    void* p = nullptr;
    cudaGetSymbolAddress(&p, s);
    return (float*)p;
}

extern "C" void kernel_launch(void* const* d_in, const int* in_sizes, int n_in,
                              void* d_out, int out_size)
{
    (void)in_sizes; (void)n_in; (void)out_size;

    const float* rec    = (const float*)d_in[0];
    const float* codes  = (const float*)d_in[1];
    const float* snd    = (const float*)d_in[2];
    const float* ln_r_g = (const float*)d_in[3];
    const float* ln_r_b = (const float*)d_in[4];
    const float* ln_s_g = (const float*)d_in[5];
    const float* ln_s_b = (const float*)d_in[6];
    const float* Wq  = (const float*)d_in[7];
    const float* bq  = (const float*)d_in[8];
    const float* Wmq = (const float*)d_in[9];
    const float* Wk  = (const float*)d_in[10];
    // d_in[11] = bk: constant over v -> softmax-invariant; intentionally unused
    const float* Wmk = (const float*)d_in[12];
    const float* Wv  = (const float*)d_in[13];
    const float* bv  = (const float*)d_in[14];
    const float* Wmv = (const float*)d_in[15];
    const float* We  = (const float*)d_in[16];
    const float* be  = (const float*)d_in[17];
    const float* Wme = (const float*)d_in[18];
    const float* gam = (const float*)d_in[19];
    float* out = (float*)d_out;

    float* MQ   = sym(g_MQ);
    float* MK   = sym(g_MK);
    float* MV   = sym(g_MV);
    float* ME   = sym(g_ME);
    float* qmod = sym(g_qmod);
    float* Q    = sym(g_Q);
    float* sln  = sym(g_sln);
    float* Aq   = sym(g_A);
    float* S    = sym(g_S);
    float* T    = sym(g_T);
    float* msg  = sym(g_msg);

    // G1: code modulations  [256 x 384] @ [384 x N]
    gemm_k<false><<<dim3(12, 4, 1), 256>>>(codes, Wmq, MQ, CD, CD, D, D, 0, 0, 0, EpiNone{});
    gemm_k<false><<<dim3(12, 4, 1), 256>>>(codes, Wmk, MK, CD, CD, D, D, 0, 0, 0, EpiNone{});
    gemm_k<false><<<dim3(12, 4, 1), 256>>>(codes, Wmv, MV, CD, CD, D, D, 0, 0, 0, EpiNone{});
    gemm_k<false><<<dim3( 8, 4, 1), 256>>>(codes, Wme, ME, CD, CD, INNER, INNER, 0, 0, 0, EpiNone{});

    // LayerNorms
    ln_k<<<BV, 256>>>(snd, ln_s_g, ln_s_b, sln);
    ln_qmod_k<<<BU, 256>>>(rec, ln_r_g, ln_r_b, MQ, qmod);

    // G2: Q = qmod @ Wq + bq       [256 x 768] @ [768 x 512]
    gemm_k<false><<<dim3(8, 4, 1), 256>>>(qmod, Wq, Q, D, D, INNER, INNER, 0, 0, 0, EpiBias{bq});

    // G3: A[bu,h,d] = (Q_h · Wk_h^T)[d] * (1 + MK[bu,d]);  batched over h=z
    //     [256 x 64] @ [64 x 768]^T-access, strideA/B = 64 (head block)
    gemm_k<true><<<dim3(12, 4, Hh), 256>>>(Q, Wk, Aq, 64, INNER, INNER, Hh * D,
                                           64, 64, D, EpiMulRowMod{MK});

    // G4: scores[b,(u,h),v] = A_b @ sln_b^T / 8;  batched over b=z
    //     [512 x 768] @ [768 x 256]
    gemm_k<true><<<dim3(4, 8, Bb), 256>>>(Aq, sln, S, D, D, D, 256,
                                          (long)512 * D, (long)Vv * D, (long)512 * 256,
                                          EpiScale{0.125f});

    softmax_k<<<Bb * 512, 256>>>(S);

    // G5: T[b,(u,h),d] = W_b @ sln_b, * (1 + MV[bu,d]);  batched over b=z
    //     [512 x 256] @ [256 x 768]
    gemm_k<false><<<dim3(12, 8, Bb), 256>>>(S, sln, T, Vv, 256, D, D,
                                            (long)512 * 256, (long)Vv * D, (long)512 * D,
                                            EpiMulT{MV});

    // G6: msg[bu, h*64+c] = (T_h @ Wv_h + bv) * (1 + ME);  batched over h=z
    //     [256 x 768] @ [768 x 64]
    gemm_k<false><<<dim3(1, 4, Hh), 256>>>(T, Wv, msg, D, Hh * D, INNER, INNER,
                                           D, 64, 64, EpiMsg{bv, ME});

    // G7: out = receiver + gamma * (msg @ We + be)   [256 x 512] @ [512 x 768]
    gemm_k<false><<<dim3(12, 4, 1), 256>>>(msg, We, out, INNER, INNER, D, D,
                                           0, 0, 0, EpiFinal{rec, be, gam});
}

// round 9
// speedup vs baseline: 1.5318x; 1.5318x over previous
#include <cuda_runtime.h>

// ---------------------------------------------------------------------------
// Problem constants
// ---------------------------------------------------------------------------
constexpr int Bb    = 4;
constexpr int Uu    = 64;
constexpr int Vv    = 256;
constexpr int BU    = Bb * Uu;     // 256
constexpr int BV    = Bb * Vv;     // 1024
constexpr int D     = 768;         // STATE_DIM == IN_DIM
constexpr int CD    = 384;         // CODE_DIM
constexpr int INNER = 512;         // NUM_HEADS * HEAD_DIM
constexpr int Hh    = 8;
constexpr int BKk   = 32;

// ---------------------------------------------------------------------------
// Scratch (device globals; no allocation allowed)
// ---------------------------------------------------------------------------
__device__ float g_MQ[BU * D];
__device__ float g_MK[BU * D];
__device__ float g_MV[BU * D];
__device__ float g_ME[BU * INNER];
__device__ float g_qmod[BU * D];
__device__ float g_Q[BU * INNER];
__device__ float g_sln[BV * D];
__device__ float g_A[BU * Hh * D];       // [(bu*8+h)][d]
__device__ float g_S[Bb * 512 * 256];    // [b][(u*8+h)][v]
__device__ float g_T[BU * Hh * D];       // [(bu*8+h)][d]
__device__ float g_msg[BU * INNER];

// ---------------------------------------------------------------------------
// Double-buffered tiled fp32 GEMM core.
// C[r,c] = epi( sum_k A[r,k]*B[k,c], z, r, c )
// BT=true: B element (k,n) at B[n*ldb + k] (transposed access, coalesced on k).
// K must be a multiple of 32; M,N multiples of BM,BN (true for all calls).
// ---------------------------------------------------------------------------
template <int BM, int BN, int NT, bool BT, class Epi>
__device__ __forceinline__ void gemm_core(
    const float* __restrict__ A, const float* __restrict__ B,
    float* __restrict__ C, int K, int lda, int ldb, int ldc,
    int z, int bm, int bn, Epi epi)
{
    constexpr int TX = 16, TY = NT / 16;
    constexpr int TM = BM / TY, TN = BN / TX;
    constexpr int RA = BM * BKk / NT, RB = BN * BKk / NT;
    static_assert(TM == 4, "A microtile must be float4");
    static_assert(TN == 4 || TN == 2, "B microtile float4/float2");

    __shared__ __align__(16) float As[2][BKk][BM + 4];
    __shared__ __align__(16) float Bs[2][BKk][BN + 4];

    const int tid = threadIdx.x;
    const int tx = tid % TX;
    const int ty = tid / TX;

    float ra[RA], rb[RB];
    float acc[TM][TN] = {};

    // ---- prologue: tile 0 global -> reg -> smem[0]
    #pragma unroll
    for (int i = 0; i < RA; ++i) {
        int idx = tid + i * NT;
        ra[i] = A[(long)(bm + idx / BKk) * lda + (idx % BKk)];
    }
    #pragma unroll
    for (int i = 0; i < RB; ++i) {
        int idx = tid + i * NT;
        if constexpr (BT) rb[i] = B[(long)(bn + idx / BKk) * ldb + (idx % BKk)];
        else              rb[i] = B[(long)(idx / BN) * ldb + bn + (idx % BN)];
    }
    #pragma unroll
    for (int i = 0; i < RA; ++i) {
        int idx = tid + i * NT;
        As[0][idx % BKk][idx / BKk] = ra[i];
    }
    #pragma unroll
    for (int i = 0; i < RB; ++i) {
        int idx = tid + i * NT;
        if constexpr (BT) Bs[0][idx % BKk][idx / BKk] = rb[i];
        else              Bs[0][idx / BN][idx % BN] = rb[i];
    }
    __syncthreads();

    const int nI = K / BKk;
    for (int it = 0; it < nI; ++it) {
        const int s = it & 1;

        // ---- prefetch tile it+1 into registers (overlaps with FMA block)
        if (it + 1 < nI) {
            const int k0 = (it + 1) * BKk;
            #pragma unroll
            for (int i = 0; i < RA; ++i) {
                int idx = tid + i * NT;
                ra[i] = A[(long)(bm + idx / BKk) * lda + k0 + (idx % BKk)];
            }
            #pragma unroll
            for (int i = 0; i < RB; ++i) {
                int idx = tid + i * NT;
                if constexpr (BT) rb[i] = B[(long)(bn + idx / BKk) * ldb + k0 + (idx % BKk)];
                else              rb[i] = B[(long)(k0 + idx / BN) * ldb + bn + (idx % BN)];
            }
        }

        // ---- compute from smem[s]
        #pragma unroll
        for (int k = 0; k < BKk; ++k) {
            float a4[TM], b4[TN];
            *(float4*)a4 = *(const float4*)&As[s][k][ty * TM];
            if constexpr (TN == 4)
                *(float4*)b4 = *(const float4*)&Bs[s][k][tx * TN];
            else
                *(float2*)b4 = *(const float2*)&Bs[s][k][tx * TN];
            #pragma unroll
            for (int i = 0; i < TM; ++i)
                #pragma unroll
                for (int j = 0; j < TN; ++j)
                    acc[i][j] = fmaf(a4[i], b4[j], acc[i][j]);
        }

        // ---- drain registers into smem[s^1]
        if (it + 1 < nI) {
            #pragma unroll
            for (int i = 0; i < RA; ++i) {
                int idx = tid + i * NT;
                As[s ^ 1][idx % BKk][idx / BKk] = ra[i];
            }
            #pragma unroll
            for (int i = 0; i < RB; ++i) {
                int idx = tid + i * NT;
                if constexpr (BT) Bs[s ^ 1][idx % BKk][idx / BKk] = rb[i];
                else              Bs[s ^ 1][idx / BN][idx % BN] = rb[i];
            }
        }
        __syncthreads();
    }

    #pragma unroll
    for (int i = 0; i < TM; ++i) {
        int r = bm + ty * TM + i;
        #pragma unroll
        for (int j = 0; j < TN; ++j) {
            int c = bn + tx * TN + j;
            C[(long)r * ldc + c] = epi(acc[i][j], z, r, c);
        }
    }
}

template <int BM, int BN, int NT, bool BT, class Epi>
__global__ void __launch_bounds__(NT)
gemm_k(const float* __restrict__ Ag, const float* __restrict__ Bg,
       float* __restrict__ Cg, int K, int lda, int ldb, int ldc,
       long sA, long sB, long sC, Epi epi)
{
    const int z = blockIdx.z;
    gemm_core<BM, BN, NT, BT, Epi>(Ag + (long)z * sA, Bg + (long)z * sB,
                                   Cg + (long)z * sC, K, lda, ldb, ldc,
                                   z, blockIdx.y * BM, blockIdx.x * BN, epi);
}

// ---------------------------------------------------------------------------
// Epilogues
// ---------------------------------------------------------------------------
struct EpiNone {
    __device__ float operator()(float a, int, int, int) const { return a; }
};
struct EpiBias {  // + b[col]
    const float* b;
    __device__ float operator()(float a, int, int, int c) const { return a + b[c]; }
};
struct EpiScale {
    float s;
    __device__ float operator()(float a, int, int, int) const { return a * s; }
};
struct EpiMulRowMod {  // G3: * (1 + m[row*768 + col])
    const float* m;
    __device__ float operator()(float a, int, int r, int c) const {
        return a * (1.f + m[r * 768 + c]);
    }
};
struct EpiMulT {  // G5: * (1 + MV[bu*768 + d]); rows (u*8+h), batch b=z
    const float* mv;
    __device__ float operator()(float a, int z, int r, int c) const {
        int bu = z * 64 + (r >> 3);
        return a * (1.f + mv[bu * 768 + c]);
    }
};
struct EpiMsg {  // G6: (acc + bv[h*64+c]) * (1 + ME[bu*512 + h*64+c]); z = h
    const float* bv;
    const float* me;
    __device__ float operator()(float a, int z, int r, int c) const {
        int idx = z * 64 + c;
        return (a + bv[idx]) * (1.f + me[r * 512 + idx]);
    }
};
struct EpiFinal {  // G7: receiver + gamma * (acc + be)
    const float* rec;
    const float* be;
    const float* gam;
    __device__ float operator()(float a, int, int r, int c) const {
        return rec[(long)r * 768 + c] + gam[c] * (a + be[c]);
    }
};

// ---------------------------------------------------------------------------
// Merged modulation GEMM: A = codes for all 4, z selects (W, C, ldc).
// grid (12, 4, 4); z=3 (Wme, N=512) uses only 8 x-blocks.
// ---------------------------------------------------------------------------
struct ModArgs {
    const float* W[4];
    float*       C[4];
    int          ld[4];
    int          nbx[4];
};

__global__ void __launch_bounds__(256)
modgemm_k(const float* __restrict__ codes, ModArgs ma)
{
    const int z = blockIdx.z;
    if ((int)blockIdx.x >= ma.nbx[z]) return;
    gemm_core<64, 64, 256, false, EpiNone>(
        codes, ma.W[z], ma.C[z], CD, CD, ma.ld[z], ma.ld[z],
        z, blockIdx.y * 64, blockIdx.x * 64, EpiNone{});
}

// ---------------------------------------------------------------------------
// LayerNorm kernels (row = one 256-thread block, dim 768)
// ---------------------------------------------------------------------------
__device__ __forceinline__ void reduce2_768(float& s, float& s2)
{
    __shared__ float2 sm[8];
    #pragma unroll
    for (int o = 16; o; o >>= 1) {
        s  += __shfl_xor_sync(0xffffffffu, s,  o);
        s2 += __shfl_xor_sync(0xffffffffu, s2, o);
    }
    if ((threadIdx.x & 31) == 0) sm[threadIdx.x >> 5] = make_float2(s, s2);
    __syncthreads();
    s = 0.f; s2 = 0.f;
    #pragma unroll
    for (int i = 0; i < 8; ++i) { s += sm[i].x; s2 += sm[i].y; }
}

__global__ void ln_k(const float* __restrict__ xin, const float* __restrict__ g,
                     const float* __restrict__ bb, float* __restrict__ out)
{
    int row = blockIdx.x;
    const float* x = xin + (long)row * 768;
    float v[3], s = 0.f, s2 = 0.f;
    #pragma unroll
    for (int i = 0; i < 3; ++i) {
        v[i] = x[threadIdx.x + 256 * i];
        s += v[i]; s2 += v[i] * v[i];
    }
    reduce2_768(s, s2);
    float mu = s * (1.f / 768.f);
    float var = s2 * (1.f / 768.f) - mu * mu;
    float inv = rsqrtf(var + 1e-5f);
    #pragma unroll
    for (int i = 0; i < 3; ++i) {
        int d = threadIdx.x + 256 * i;
        out[(long)row * 768 + d] = (v[i] - mu) * inv * g[d] + bb[d];
    }
}

__global__ void ln_qmod_k(const float* __restrict__ rec, const float* __restrict__ g,
                          const float* __restrict__ bb, const float* __restrict__ MQ,
                          float* __restrict__ qmod)
{
    int row = blockIdx.x;
    const float* x = rec + (long)row * 768;
    float v[3], s = 0.f, s2 = 0.f;
    #pragma unroll
    for (int i = 0; i < 3; ++i) {
        v[i] = x[threadIdx.x + 256 * i];
        s += v[i]; s2 += v[i] * v[i];
    }
    reduce2_768(s, s2);
    float mu = s * (1.f / 768.f);
    float var = s2 * (1.f / 768.f) - mu * mu;
    float inv = rsqrtf(var + 1e-5f);
    #pragma unroll
    for (int i = 0; i < 3; ++i) {
        int d = threadIdx.x + 256 * i;
        float y = (v[i] - mu) * inv * g[d] + bb[d];
        qmod[(long)row * 768 + d] = y * (1.f + MQ[(long)row * 768 + d]);
    }
}

// ---------------------------------------------------------------------------
// Softmax over v (256) — one block per (b, u, h) row
// ---------------------------------------------------------------------------
__global__ void softmax_k(float* __restrict__ S)
{
    int row = blockIdx.x;
    float v = S[(long)row * 256 + threadIdx.x];
    __shared__ float sm[8];

    float m = v;
    #pragma unroll
    for (int o = 16; o; o >>= 1) m = fmaxf(m, __shfl_xor_sync(0xffffffffu, m, o));
    if ((threadIdx.x & 31) == 0) sm[threadIdx.x >> 5] = m;
    __syncthreads();
    m = sm[0];
    #pragma unroll
    for (int i = 1; i < 8; ++i) m = fmaxf(m, sm[i]);
    float e = __expf(v - m);
    __syncthreads();

    float su = e;
    #pragma unroll
    for (int o = 16; o; o >>= 1) su += __shfl_xor_sync(0xffffffffu, su, o);
    if ((threadIdx.x & 31) == 0) sm[threadIdx.x >> 5] = su;
    __syncthreads();
    su = 0.f;
    #pragma unroll
    for (int i = 0; i < 8; ++i) su += sm[i];

    S[(long)row * 256 + threadIdx.x] = e / su;
}

// ---------------------------------------------------------------------------
// Launch
// ---------------------------------------------------------------------------
static float* sym(const void* s)
{
    void* p = nullptr;
    cudaGetSymbolAddress(&p, s);
    return (float*)p;
}

extern "C" void kernel_launch(void* const* d_in, const int* in_sizes, int n_in,
                              void* d_out, int out_size)
{
    (void)in_sizes; (void)n_in; (void)out_size;

    const float* rec    = (const float*)d_in[0];
    const float* codes  = (const float*)d_in[1];
    const float* snd    = (const float*)d_in[2];
    const float* ln_r_g = (const float*)d_in[3];
    const float* ln_r_b = (const float*)d_in[4];
    const float* ln_s_g = (const float*)d_in[5];
    const float* ln_s_b = (const float*)d_in[6];
    const float* Wq  = (const float*)d_in[7];
    const float* bq  = (const float*)d_in[8];
    const float* Wmq = (const float*)d_in[9];
    const float* Wk  = (const float*)d_in[10];
    // d_in[11] = bk: constant over v -> softmax-invariant; intentionally unused
    const float* Wmk = (const float*)d_in[12];
    const float* Wv  = (const float*)d_in[13];
    const float* bv  = (const float*)d_in[14];
    const float* Wmv = (const float*)d_in[15];
    const float* We  = (const float*)d_in[16];
    const float* be  = (const float*)d_in[17];
    const float* Wme = (const float*)d_in[18];
    const float* gam = (const float*)d_in[19];
    float* out = (float*)d_out;

    float* MQ   = sym(g_MQ);
    float* MK   = sym(g_MK);
    float* MV   = sym(g_MV);
    float* ME   = sym(g_ME);
    float* qmod = sym(g_qmod);
    float* Q    = sym(g_Q);
    float* sln  = sym(g_sln);
    float* Aq   = sym(g_A);
    float* S    = sym(g_S);
    float* T    = sym(g_T);
    float* msg  = sym(g_msg);

    // G1 (merged): all 4 code modulations in one launch — 176 active blocks
    ModArgs ma;
    ma.W[0] = Wmq; ma.W[1] = Wmk; ma.W[2] = Wmv; ma.W[3] = Wme;
    ma.C[0] = MQ;  ma.C[1] = MK;  ma.C[2] = MV;  ma.C[3] = ME;
    ma.ld[0] = D;  ma.ld[1] = D;  ma.ld[2] = D;  ma.ld[3] = INNER;
    ma.nbx[0] = 12; ma.nbx[1] = 12; ma.nbx[2] = 12; ma.nbx[3] = 8;
    modgemm_k<<<dim3(12, 4, 4), 256>>>(codes, ma);

    // LayerNorms
    ln_k<<<BV, 256>>>(snd, ln_s_g, ln_s_b, sln);
    ln_qmod_k<<<BU, 256>>>(rec, ln_r_g, ln_r_b, MQ, qmod);

    // G2: Q = qmod @ Wq + bq   [256 x 768] @ [768 x 512] — 128 blocks (32x32)
    gemm_k<32, 32, 128, false><<<dim3(16, 8, 1), 128>>>(
        qmod, Wq, Q, D, D, INNER, INNER, 0, 0, 0, EpiBias{bq});

    // G3: A[bu,h,d] = (Q_h . Wk_h^T)[d] * (1+MK); batched h=z — 384 blocks
    gemm_k<64, 64, 256, true><<<dim3(12, 4, Hh), 256>>>(
        Q, Wk, Aq, 64, INNER, INNER, Hh * D, 64, 64, D, EpiMulRowMod{MK});

    // G4: scores = A_b @ sln_b^T / 8; batched b=z — 256 blocks (32x64)
    gemm_k<32, 64, 128, true><<<dim3(4, 16, Bb), 128>>>(
        Aq, sln, S, D, D, D, 256,
        (long)512 * D, (long)Vv * D, (long)512 * 256, EpiScale{0.125f});

    softmax_k<<<Bb * 512, 256>>>(S);

    // G5: T = W_b @ sln_b, * (1+MV); batched b=z — 384 blocks
    gemm_k<64, 64, 256, false><<<dim3(12, 8, Bb), 256>>>(
        S, sln, T, Vv, 256, D, D,
        (long)512 * 256, (long)Vv * D, (long)512 * D, EpiMulT{MV});

    // G6: msg = (T_h @ Wv_h + bv) * (1+ME); batched h=z — 128 blocks (32x32)
    gemm_k<32, 32, 128, false><<<dim3(2, 8, Hh), 128>>>(
        T, Wv, msg, D, Hh * D, INNER, INNER, (long)D, 64, 64, EpiMsg{bv, ME});

    // G7: out = rec + gamma * (msg @ We + be) — 192 blocks (32x32)
    gemm_k<32, 32, 128, false><<<dim3(24, 8, 1), 128>>>(
        msg, We, out, INNER, INNER, D, D, 0, 0, 0, EpiFinal{rec, be, gam});
}